// round 12
// baseline (speedup 1.0000x reference)
#include <cuda_runtime.h>
#include <cuda_fp16.h>
#include <cstdint>

// Problem constants
#define BATCH 2
#define SEQ   2048
#define DIM   1024
#define HEADS 16
#define HDIM  64
#define MROWS (BATCH*SEQ)   // 4096
#define QKLD  (2*DIM)       // Q|K buffer row stride
#define QSCALE2 0.18033688011112042f   // 0.125 * log2(e), folded into Wq

// Scratch (allocation-free rule: __device__ globals)
__device__ __half g_h16[MROWS * DIM];      // H in fp16
__device__ __half g_w16[4 * DIM * DIM];    // WqT(scaled)|WkT|WvT|WoT, fp16 [N][K]
__device__ __half g_qk [MROWS * QKLD];     // Q|K fp16, row stride 2048
__device__ __half g_vt [MROWS * DIM];      // V transposed [b][h][d][s], fp16
__device__ __half g_ao [MROWS * DIM];      // attention out, fp16

// ---------------------------------------------------------------------------
// helpers
// ---------------------------------------------------------------------------
__device__ __forceinline__ uint32_t smem_u32(const void* p) {
    uint32_t a;
    asm("{ .reg .u64 t; cvta.to.shared.u64 t, %1; cvt.u32.u64 %0, t; }"
        : "=r"(a) : "l"(p));
    return a;
}
__device__ __forceinline__ void cp16(uint32_t dst, const void* src) {
    asm volatile("cp.async.cg.shared.global [%0], [%1], 16;"
                 :: "r"(dst), "l"(src));
}
#define CP_COMMIT() asm volatile("cp.async.commit_group;" ::: "memory")
#define CP_WAIT2()  asm volatile("cp.async.wait_group 2;" ::: "memory")
#define CP_WAIT1()  asm volatile("cp.async.wait_group 1;" ::: "memory")
#define CP_WAIT0()  asm volatile("cp.async.wait_group 0;" ::: "memory")

__device__ __forceinline__ void mma_f16(float* c,
    uint32_t a0, uint32_t a1, uint32_t a2, uint32_t a3,
    uint32_t b0, uint32_t b1)
{
    asm volatile(
        "mma.sync.aligned.m16n8k16.row.col.f32.f16.f16.f32 "
        "{%0,%1,%2,%3}, {%4,%5,%6,%7}, {%8,%9}, {%0,%1,%2,%3};"
        : "+f"(c[0]), "+f"(c[1]), "+f"(c[2]), "+f"(c[3])
        : "r"(a0), "r"(a1), "r"(a2), "r"(a3), "r"(b0), "r"(b1));
}
__device__ __forceinline__ void ldsm4(uint32_t& r0, uint32_t& r1,
                                      uint32_t& r2, uint32_t& r3, uint32_t addr)
{
    asm volatile("ldmatrix.sync.aligned.m8n8.x4.shared.b16 {%0,%1,%2,%3}, [%4];"
                 : "=r"(r0), "=r"(r1), "=r"(r2), "=r"(r3) : "r"(addr));
}

// ---------------------------------------------------------------------------
// Fused prep: z=0..3 transpose+convert weights (Wq scaled); z=4..7 convert H.
// ---------------------------------------------------------------------------
__global__ __launch_bounds__(256) void prep_kernel(
    const float* __restrict__ H,
    const float* __restrict__ W0, const float* __restrict__ W1,
    const float* __restrict__ W2, const float* __restrict__ W3,
    __half* __restrict__ WT, __half* __restrict__ H16)
{
    const int z = blockIdx.z;
    if (z < 4) {
        __shared__ float t[32][33];
        const float* W = (z == 0) ? W0 : (z == 1) ? W1 : (z == 2) ? W2 : W3;
        const float sc = (z == 0) ? QSCALE2 : 1.0f;
        __half* D = WT + (size_t)z * DIM * DIM;
        int bx = blockIdx.x * 32, by = blockIdx.y * 32;
        int x = bx + threadIdx.x;
        #pragma unroll
        for (int j = 0; j < 32; j += 8)
            t[threadIdx.y + j][threadIdx.x] = W[(size_t)(by + threadIdx.y + j) * DIM + x];
        __syncthreads();
        x = by + threadIdx.x;
        #pragma unroll
        for (int j = 0; j < 32; j += 8)
            D[(size_t)(bx + threadIdx.y + j) * DIM + x] =
                __float2half_rn(sc * t[threadIdx.x][threadIdx.y + j]);
    } else {
        const int rbase = (z - 4) * 1024 + blockIdx.y * 32 + threadIdx.y;
        const int col = blockIdx.x * 32 + threadIdx.x;
        #pragma unroll
        for (int j = 0; j < 32; j += 8) {
            size_t idx = (size_t)(rbase + j) * DIM + col;
            H16[idx] = __float2half_rn(H[idx]);
        }
    }
}

// ---------------------------------------------------------------------------
// fp16 mma GEMM: C[4096, N_out] = A[4096,1024] @ BT[N_out,1024]^T
// 4-stage cp.async, ONE barrier per chunk. QKV: fp16 out (V transposed to VT);
// Wo: fp32 out.
// ---------------------------------------------------------------------------
#define BM 128
#define BN 128
#define BK 32
#define TILE_HALF (128 * 40)           // 5120 halves, row = 80 B
#define STAGE_BYTES (2 * TILE_HALF * 2)  // 20480
#define GEMM_SMEM (4 * STAGE_BYTES)    // 81920 B
#define NCHUNK (DIM / BK)              // 32

template<bool QKV>
__global__ __launch_bounds__(256, 2) void gemm_f16_kernel(
    const __half* __restrict__ A, const __half* __restrict__ BT,
    void* __restrict__ Cv, int ldc, __half* __restrict__ VT)
{
    extern __shared__ char sm[];
    const uint32_t sbase = smem_u32(sm);
    const int tid = threadIdx.x;
    const int wid = tid >> 5;
    const int lid = tid & 31;
    const int wm  = wid >> 2;
    const int wn  = wid & 3;
    const int g   = lid >> 2;
    const int tg  = lid & 3;
    const int bm = blockIdx.y * BM;
    const int bn = blockIdx.x * BN;

    const int xr16 = lid & 15;
    const uint32_t xh16 = (uint32_t)((lid >> 4) * 16);
    const int bq = lid >> 3, br = lid & 7;
    const uint32_t bRow = (uint32_t)(((bq >> 1) * 8) + br);
    const uint32_t bKh  = (uint32_t)((bq & 1) * 16);

    float acc[4][4][4] = {};

    auto load_chunk = [&](int c, int stg) {
        const __half* Ag = A  + (size_t)bm * DIM + c * BK;
        const __half* Bg = BT + (size_t)bn * DIM + c * BK;
        const uint32_t aB = sbase + (uint32_t)stg * STAGE_BYTES;
        const uint32_t bB = aB + TILE_HALF * 2;
        #pragma unroll
        for (int i = 0; i < 2; i++) {
            int idx = tid + i * 256;
            int r = idx >> 2, s = idx & 3;
            uint32_t off = (uint32_t)(r * 80 + s * 16);
            cp16(aB + off, Ag + (size_t)r * DIM + s * 8);
            cp16(bB + off, Bg + (size_t)r * DIM + s * 8);
        }
    };

    auto compute = [&](int stg) {
        const uint32_t aB = sbase + (uint32_t)stg * STAGE_BYTES;
        const uint32_t bB = aB + TILE_HALF * 2;
        const uint32_t aLane = aB + (uint32_t)(wm * 64 + xr16) * 80 + xh16;
        const uint32_t bLane = bB + (uint32_t)(wn * 32) * 80 + bRow * 80 + bKh;
        #pragma unroll
        for (int kk = 0; kk < 2; kk++) {
            const uint32_t koff = (uint32_t)kk * 32;
            uint32_t af[4][4], bf[4][2];
            #pragma unroll
            for (int fm = 0; fm < 4; fm++)
                ldsm4(af[fm][0], af[fm][1], af[fm][2], af[fm][3],
                      aLane + (uint32_t)(fm * 16) * 80 + koff);
            #pragma unroll
            for (int fnp = 0; fnp < 2; fnp++) {
                uint32_t r0, r1, r2, r3;
                ldsm4(r0, r1, r2, r3, bLane + (uint32_t)(fnp * 16) * 80 + koff);
                bf[2*fnp][0]   = r0; bf[2*fnp][1]   = r1;
                bf[2*fnp+1][0] = r2; bf[2*fnp+1][1] = r3;
            }
            #pragma unroll
            for (int fm = 0; fm < 4; fm++)
                #pragma unroll
                for (int fn = 0; fn < 4; fn++)
                    mma_f16(acc[fm][fn], af[fm][0], af[fm][1], af[fm][2], af[fm][3],
                            bf[fn][0], bf[fn][1]);
        }
    };

    load_chunk(0, 0); CP_COMMIT();
    load_chunk(1, 1); CP_COMMIT();
    load_chunk(2, 2); CP_COMMIT();
    for (int c = 0; c < NCHUNK; c++) {
        // chunk c ready when <= (#groups issued beyond c) outstanding
        if (c <= NCHUNK - 3)      { CP_WAIT2(); }
        else if (c == NCHUNK - 2) { CP_WAIT1(); }
        else                      { CP_WAIT0(); }
        __syncthreads();          // single barrier: stage (c+3)%4 free (read at c-1)
        compute(c & 3);
        if (c + 3 < NCHUNK) { load_chunk(c + 3, (c + 3) & 3); CP_COMMIT(); }
    }

    if (QKV) {
        if (bn >= 2 * DIM) {
            #pragma unroll
            for (int fm = 0; fm < 4; fm++) {
                const int row = bm + wm * 64 + fm * 16 + g;
                const int bb = row >> 11, s = row & (SEQ - 1);
                #pragma unroll
                for (int fn = 0; fn < 4; fn++) {
                    const int colv = (bn - 2 * DIM) + wn * 32 + fn * 8 + tg * 2;
                    const int h = colv >> 6, d = colv & 63;
                    __half* vb = VT + ((size_t)((bb * HEADS + h) * HDIM + d)) * SEQ;
                    vb[s]           = __float2half_rn(acc[fm][fn][0]);
                    vb[SEQ + s]     = __float2half_rn(acc[fm][fn][1]);
                    vb[s + 8]       = __float2half_rn(acc[fm][fn][2]);
                    vb[SEQ + s + 8] = __float2half_rn(acc[fm][fn][3]);
                }
            }
        } else {
            __half* C = (__half*)Cv;
            #pragma unroll
            for (int fm = 0; fm < 4; fm++) {
                const int row = bm + wm * 64 + fm * 16 + g;
                #pragma unroll
                for (int fn = 0; fn < 4; fn++) {
                    const int col = bn + wn * 32 + fn * 8 + tg * 2;
                    *(__half2*)(C + (size_t)row * ldc + col) =
                        __floats2half2_rn(acc[fm][fn][0], acc[fm][fn][1]);
                    *(__half2*)(C + (size_t)(row + 8) * ldc + col) =
                        __floats2half2_rn(acc[fm][fn][2], acc[fm][fn][3]);
                }
            }
        }
        return;
    }

    float* C = (float*)Cv;
    #pragma unroll
    for (int fm = 0; fm < 4; fm++) {
        const int row = bm + wm * 64 + fm * 16 + g;
        #pragma unroll
        for (int fn = 0; fn < 4; fn++) {
            const int col = bn + wn * 32 + fn * 8 + tg * 2;
            *(float2*)(C + (size_t)row * ldc + col) =
                make_float2(acc[fm][fn][0], acc[fm][fn][1]);
            *(float2*)(C + (size_t)(row + 8) * ldc + col) =
                make_float2(acc[fm][fn][2], acc[fm][fn][3]);
        }
    }
}

// ---------------------------------------------------------------------------
// fp16 flash attention, deep-staged + single barrier per KV tile.
// K 3-stage, V 4-stage, P double-buffered, mask 3-stage.
// Iter i: S(i) -> PV(i-1) -> softmax(i) -> prefetch KV(i+2).
// ---------------------------------------------------------------------------
#define AKEYS 64
#define KS_B   0                        // 3 x 9216 = 27648
#define VS_B   27648                    // 4 x 9216 = 36864
#define PS_B   64512                    // 2 x 18432 = 36864 (Q staged in buf 0)
#define MSK_B  101376                   // 3 x 256
#define ATT_SMEM 102144
#define NKT (SEQ / AKEYS)               // 32

__global__ __launch_bounds__(256, 2) void attn_f16_kernel(
    const __half* __restrict__ qk, const __half* __restrict__ vt,
    const int* __restrict__ mask, __half* __restrict__ o)
{
    extern __shared__ char sA[];
    const uint32_t sbase = smem_u32(sA);

    const int b  = blockIdx.z;
    const int h  = blockIdx.y;
    const int qt = blockIdx.x;
    const int tid = threadIdx.x;
    const int w   = tid >> 5;
    const int lid = tid & 31;
    const int g   = lid >> 2;
    const int tg  = lid & 3;
    const int xr16 = lid & 15;
    const uint32_t xh16 = (uint32_t)((lid >> 4) * 16);
    const int bq = lid >> 3, br = lid & 7;
    const uint32_t bRowOff = (uint32_t)(((bq >> 1) * 8) + br) * 144 +
                             (uint32_t)((bq & 1) * 16);

    const int qr0 = w * 16 + g;
    const int qr1 = qr0 + 8;

    // ---- KV tile loader: K+msk stage it%3, V stage it%4, one commit group ----
    auto load_kv = [&](int it) {
        const __half* Kg = qk + ((size_t)(b * SEQ + it * AKEYS)) * QKLD + DIM + h * HDIM;
        const __half* Vg = vt + ((size_t)((b * HEADS + h) * HDIM)) * SEQ + it * AKEYS;
        const uint32_t kB = sbase + KS_B + (uint32_t)(it % 3) * 9216;
        const uint32_t vB = sbase + VS_B + (uint32_t)(it & 3) * 9216;
        #pragma unroll
        for (int i = 0; i < 2; i++) {
            int idx = tid + i * 256;
            int r = idx >> 3, s = idx & 7;
            uint32_t off = (uint32_t)(r * 144 + s * 16);
            cp16(kB + off, Kg + (size_t)r * QKLD + s * 8);
            cp16(vB + off, Vg + (size_t)r * SEQ + s * 8);
        }
        if (tid < 16)
            cp16(sbase + MSK_B + (uint32_t)(it % 3) * 256 + (uint32_t)tid * 16,
                 mask + b * SEQ + it * AKEYS + tid * 4);
    };

    // ---- prologue: Q into P buffer 0; prefetch KV(0), KV(1) ----
    const __half* Qg = qk + ((size_t)(b * SEQ + qt * 128)) * QKLD + h * HDIM;
    #pragma unroll
    for (int i = 0; i < 4; i++) {
        int idx = tid + i * 256;
        int r = idx >> 3, s = idx & 7;
        cp16(sbase + PS_B + (uint32_t)(r * 144 + s * 16), Qg + (size_t)r * QKLD + s * 8);
    }
    CP_COMMIT();
    load_kv(0); CP_COMMIT();
    load_kv(1); CP_COMMIT();
    CP_WAIT2();                 // Q group done
    __syncthreads();

    uint32_t aq[4][4];
    {
        const uint32_t qLane = sbase + PS_B + (uint32_t)(w * 16 + xr16) * 144 + xh16;
        #pragma unroll
        for (int ks = 0; ks < 4; ks++)
            ldsm4(aq[ks][0], aq[ks][1], aq[ks][2], aq[ks][3],
                  qLane + (uint32_t)ks * 32);
    }
    __syncthreads();            // Q frags read; P buffer 0 reusable

    float m0 = -3.0e38f, m1 = -3.0e38f, l0 = 0.0f, l1 = 0.0f;
    float oacc[8][4] = {};

    for (int it = 0; it < NKT; it++) {
        if (it <= NKT - 2) { CP_WAIT1(); } else { CP_WAIT0(); }
        __syncthreads();        // single barrier per tile

        const uint32_t kTile = sbase + KS_B + (uint32_t)(it % 3) * 9216;
        const int* Mi = (const int*)(sA + MSK_B + (it % 3) * 256);

        // ---- S = Q @ K^T (log2 units; Q pre-scaled) ----
        float sacc[8][4] = {};
        #pragma unroll
        for (int ntp = 0; ntp < 4; ntp++) {
            const uint32_t kNtp = kTile + bRowOff + (uint32_t)(ntp * 16) * 144;
            #pragma unroll
            for (int ks = 0; ks < 4; ks++) {
                uint32_t r0, r1, r2, r3;
                ldsm4(r0, r1, r2, r3, kNtp + (uint32_t)ks * 32);
                mma_f16(sacc[2*ntp],   aq[ks][0], aq[ks][1], aq[ks][2], aq[ks][3], r0, r1);
                mma_f16(sacc[2*ntp+1], aq[ks][0], aq[ks][1], aq[ks][2], aq[ks][3], r2, r3);
            }
        }

        // ---- PV(it-1): overlaps softmax below ----
        if (it > 0) {
            const uint32_t vPrev = sbase + VS_B + (uint32_t)((it - 1) & 3) * 9216;
            const uint32_t pPrev = sbase + PS_B + (uint32_t)((it - 1) & 1) * 18432 +
                                   (uint32_t)(w * 16 + xr16) * 144 + xh16;
            #pragma unroll
            for (int kt = 0; kt < 4; kt++) {
                uint32_t a0, a1, a2, a3;
                ldsm4(a0, a1, a2, a3, pPrev + (uint32_t)kt * 32);
                #pragma unroll
                for (int dtp = 0; dtp < 4; dtp++) {
                    uint32_t v0, v1, v2, v3;
                    ldsm4(v0, v1, v2, v3,
                          vPrev + bRowOff + (uint32_t)(dtp * 16) * 144 + (uint32_t)kt * 32);
                    mma_f16(oacc[2*dtp],   a0, a1, a2, a3, v0, v1);
                    mma_f16(oacc[2*dtp+1], a0, a1, a2, a3, v2, v3);
                }
            }
        }

        // ---- softmax(it) ----
        #pragma unroll
        for (int nt = 0; nt < 8; nt++) {
            int c = nt * 8 + 2 * tg;
            if (Mi[c]     == 0) { sacc[nt][0] = -3.0e38f; sacc[nt][2] = -3.0e38f; }
            if (Mi[c + 1] == 0) { sacc[nt][1] = -3.0e38f; sacc[nt][3] = -3.0e38f; }
        }
        float tm0 = -3.0e38f, tm1 = -3.0e38f;
        #pragma unroll
        for (int nt = 0; nt < 8; nt++) {
            tm0 = fmaxf(tm0, fmaxf(sacc[nt][0], sacc[nt][1]));
            tm1 = fmaxf(tm1, fmaxf(sacc[nt][2], sacc[nt][3]));
        }
        tm0 = fmaxf(tm0, __shfl_xor_sync(0xffffffffu, tm0, 1));
        tm0 = fmaxf(tm0, __shfl_xor_sync(0xffffffffu, tm0, 2));
        tm1 = fmaxf(tm1, __shfl_xor_sync(0xffffffffu, tm1, 1));
        tm1 = fmaxf(tm1, __shfl_xor_sync(0xffffffffu, tm1, 2));

        float mn0 = fmaxf(m0, tm0), mn1 = fmaxf(m1, tm1);
        float corr0 = exp2f(m0 - mn0), corr1 = exp2f(m1 - mn1);
        m0 = mn0; m1 = mn1;

        const uint32_t pCur = (uint32_t)(PS_B + (it & 1) * 18432);
        float sum0 = 0.0f, sum1 = 0.0f;
        #pragma unroll
        for (int nt = 0; nt < 8; nt++) {
            float p0 = exp2f(sacc[nt][0] - mn0);
            float p1 = exp2f(sacc[nt][1] - mn0);
            float p2 = exp2f(sacc[nt][2] - mn1);
            float p3 = exp2f(sacc[nt][3] - mn1);
            sum0 += p0 + p1; sum1 += p2 + p3;
            int c = nt * 8 + 2 * tg;
            *(__half2*)(sA + pCur + (qr0 * 144 + c * 2)) = __floats2half2_rn(p0, p1);
            *(__half2*)(sA + pCur + (qr1 * 144 + c * 2)) = __floats2half2_rn(p2, p3);
        }
        sum0 += __shfl_xor_sync(0xffffffffu, sum0, 1);
        sum0 += __shfl_xor_sync(0xffffffffu, sum0, 2);
        sum1 += __shfl_xor_sync(0xffffffffu, sum1, 1);
        sum1 += __shfl_xor_sync(0xffffffffu, sum1, 2);
        l0 = l0 * corr0 + sum0;
        l1 = l1 * corr1 + sum1;

        // ---- rescale oacc (after PV(it-1) accumulated) ----
        #pragma unroll
        for (int dt = 0; dt < 8; dt++) {
            oacc[dt][0] *= corr0; oacc[dt][1] *= corr0;
            oacc[dt][2] *= corr1; oacc[dt][3] *= corr1;
        }

        // ---- prefetch KV(it+2): K stage (it-1)%3, V stage (it-2)%4 — both free
        if (it + 2 < NKT) { load_kv(it + 2); CP_COMMIT(); }
    }

    // ---- final PV(NKT-1) ----
    __syncwarp();
    {
        const uint32_t vPrev = sbase + VS_B + (uint32_t)((NKT - 1) & 3) * 9216;
        const uint32_t pPrev = sbase + PS_B + (uint32_t)((NKT - 1) & 1) * 18432 +
                               (uint32_t)(w * 16 + xr16) * 144 + xh16;
        #pragma unroll
        for (int kt = 0; kt < 4; kt++) {
            uint32_t a0, a1, a2, a3;
            ldsm4(a0, a1, a2, a3, pPrev + (uint32_t)kt * 32);
            #pragma unroll
            for (int dtp = 0; dtp < 4; dtp++) {
                uint32_t v0, v1, v2, v3;
                ldsm4(v0, v1, v2, v3,
                      vPrev + bRowOff + (uint32_t)(dtp * 16) * 144 + (uint32_t)kt * 32);
                mma_f16(oacc[2*dtp],   a0, a1, a2, a3, v0, v1);
                mma_f16(oacc[2*dtp+1], a0, a1, a2, a3, v2, v3);
            }
        }
    }

    // ---- epilogue: normalize, store fp16 ----
    const float inv0 = 1.0f / l0, inv1 = 1.0f / l1;
    __half* Og = o + ((size_t)(b * SEQ + qt * 128)) * DIM + h * HDIM;
    #pragma unroll
    for (int dt = 0; dt < 8; dt++) {
        int c = dt * 8 + 2 * tg;
        *(__half2*)(Og + (size_t)qr0 * DIM + c) =
            __floats2half2_rn(oacc[dt][0] * inv0, oacc[dt][1] * inv0);
        *(__half2*)(Og + (size_t)qr1 * DIM + c) =
            __floats2half2_rn(oacc[dt][2] * inv1, oacc[dt][3] * inv1);
    }
}

// ---------------------------------------------------------------------------
// kernel_launch
// ---------------------------------------------------------------------------
extern "C" void kernel_launch(void* const* d_in, const int* in_sizes, int n_in,
                              void* d_out, int out_size)
{
    const float* H    = (const float*)d_in[0];
    const int*   mask = (const int*)  d_in[1];
    const float* Wq   = (const float*)d_in[2];
    const float* Wk   = (const float*)d_in[3];
    const float* Wv   = (const float*)d_in[4];
    const float* Wo   = (const float*)d_in[5];
    float* out = (float*)d_out;

    __half *h16, *w16, *qkp, *vtp, *aop;
    cudaGetSymbolAddress((void**)&h16, g_h16);
    cudaGetSymbolAddress((void**)&w16, g_w16);
    cudaGetSymbolAddress((void**)&qkp, g_qk);
    cudaGetSymbolAddress((void**)&vtp, g_vt);
    cudaGetSymbolAddress((void**)&aop, g_ao);
    __half* wto = w16 + 3 * DIM * DIM;

    cudaFuncSetAttribute(gemm_f16_kernel<true>,
                         cudaFuncAttributeMaxDynamicSharedMemorySize, GEMM_SMEM);
    cudaFuncSetAttribute(gemm_f16_kernel<false>,
                         cudaFuncAttributeMaxDynamicSharedMemorySize, GEMM_SMEM);
    cudaFuncSetAttribute(attn_f16_kernel,
                         cudaFuncAttributeMaxDynamicSharedMemorySize, ATT_SMEM);

    dim3 tb(32, 8), tg(DIM / 32, DIM / 32, 8);
    prep_kernel<<<tg, tb>>>(H, Wq, Wk, Wv, Wo, w16, h16);

    dim3 gqkv(3 * DIM / BN, MROWS / BM);   // (24, 32)
    gemm_f16_kernel<true><<<gqkv, 256, GEMM_SMEM>>>(h16, w16, qkp, QKLD, vtp);

    dim3 ga(SEQ / 128, HEADS, BATCH);      // (16, 16, 2)
    attn_f16_kernel<<<ga, 256, ATT_SMEM>>>(qkp, vtp, mask, aop);

    dim3 go(DIM / BN, MROWS / BM);         // (8, 32)
    gemm_f16_kernel<false><<<go, 256, GEMM_SMEM>>>(aop, wto, out, DIM, nullptr);
}

// round 13
// speedup vs baseline: 1.0064x; 1.0064x over previous
#include <cuda_runtime.h>
#include <cuda_fp16.h>
#include <cstdint>

// Problem constants
#define BATCH 2
#define SEQ   2048
#define DIM   1024
#define HEADS 16
#define HDIM  64
#define MROWS (BATCH*SEQ)   // 4096
#define QKLD  (2*DIM)       // Q|K buffer row stride
#define QSCALE2 0.18033688011112042f   // 0.125 * log2(e), folded into Wq

// Scratch (allocation-free rule: __device__ globals)
__device__ __half g_h16[MROWS * DIM];      // H in fp16
__device__ __half g_w16[4 * DIM * DIM];    // WqT(scaled)|WkT|WvT|WoT, fp16 [N][K]
__device__ __half g_qk [MROWS * QKLD];     // Q|K fp16, row stride 2048
__device__ __half g_vt [MROWS * DIM];      // V transposed [b][h][d][s], fp16
__device__ __half g_ao [MROWS * DIM];      // attention out, fp16

// ---------------------------------------------------------------------------
// helpers
// ---------------------------------------------------------------------------
__device__ __forceinline__ uint32_t smem_u32(const void* p) {
    uint32_t a;
    asm("{ .reg .u64 t; cvta.to.shared.u64 t, %1; cvt.u32.u64 %0, t; }"
        : "=r"(a) : "l"(p));
    return a;
}
__device__ __forceinline__ void cp16(uint32_t dst, const void* src) {
    asm volatile("cp.async.cg.shared.global [%0], [%1], 16;"
                 :: "r"(dst), "l"(src));
}
#define CP_COMMIT() asm volatile("cp.async.commit_group;" ::: "memory")
#define CP_WAIT2()  asm volatile("cp.async.wait_group 2;" ::: "memory")
#define CP_WAIT1()  asm volatile("cp.async.wait_group 1;" ::: "memory")
#define CP_WAIT0()  asm volatile("cp.async.wait_group 0;" ::: "memory")

__device__ __forceinline__ void mma_f16(float* c,
    uint32_t a0, uint32_t a1, uint32_t a2, uint32_t a3,
    uint32_t b0, uint32_t b1)
{
    asm volatile(
        "mma.sync.aligned.m16n8k16.row.col.f32.f16.f16.f32 "
        "{%0,%1,%2,%3}, {%4,%5,%6,%7}, {%8,%9}, {%0,%1,%2,%3};"
        : "+f"(c[0]), "+f"(c[1]), "+f"(c[2]), "+f"(c[3])
        : "r"(a0), "r"(a1), "r"(a2), "r"(a3), "r"(b0), "r"(b1));
}
__device__ __forceinline__ void ldsm4(uint32_t& r0, uint32_t& r1,
                                      uint32_t& r2, uint32_t& r3, uint32_t addr)
{
    asm volatile("ldmatrix.sync.aligned.m8n8.x4.shared.b16 {%0,%1,%2,%3}, [%4];"
                 : "=r"(r0), "=r"(r1), "=r"(r2), "=r"(r3) : "r"(addr));
}

// ---------------------------------------------------------------------------
// Fused prep: z=0..3 transpose+convert weights (Wq scaled); z=4..7 convert H.
// ---------------------------------------------------------------------------
__global__ __launch_bounds__(256) void prep_kernel(
    const float* __restrict__ H,
    const float* __restrict__ W0, const float* __restrict__ W1,
    const float* __restrict__ W2, const float* __restrict__ W3,
    __half* __restrict__ WT, __half* __restrict__ H16)
{
    const int z = blockIdx.z;
    if (z < 4) {
        __shared__ float t[32][33];
        const float* W = (z == 0) ? W0 : (z == 1) ? W1 : (z == 2) ? W2 : W3;
        const float sc = (z == 0) ? QSCALE2 : 1.0f;
        __half* D = WT + (size_t)z * DIM * DIM;
        int bx = blockIdx.x * 32, by = blockIdx.y * 32;
        int x = bx + threadIdx.x;
        #pragma unroll
        for (int j = 0; j < 32; j += 8)
            t[threadIdx.y + j][threadIdx.x] = W[(size_t)(by + threadIdx.y + j) * DIM + x];
        __syncthreads();
        x = by + threadIdx.x;
        #pragma unroll
        for (int j = 0; j < 32; j += 8)
            D[(size_t)(bx + threadIdx.y + j) * DIM + x] =
                __float2half_rn(sc * t[threadIdx.x][threadIdx.y + j]);
    } else {
        const int rbase = (z - 4) * 1024 + blockIdx.y * 32 + threadIdx.y;
        const int col = blockIdx.x * 32 + threadIdx.x;
        #pragma unroll
        for (int j = 0; j < 32; j += 8) {
            size_t idx = (size_t)(rbase + j) * DIM + col;
            H16[idx] = __float2half_rn(H[idx]);
        }
    }
}

// ---------------------------------------------------------------------------
// fp16 mma GEMM: C[4096, N_out] = A[4096,1024] @ BT[N_out,1024]^T
// 4-stage cp.async, ONE barrier per chunk. QKV: fp16 out (V transposed to VT);
// Wo: fp32 out.
// ---------------------------------------------------------------------------
#define BM 128
#define BN 128
#define BK 32
#define TILE_HALF (128 * 40)           // 5120 halves, row = 80 B
#define STAGE_BYTES (2 * TILE_HALF * 2)  // 20480
#define GEMM_SMEM (4 * STAGE_BYTES)    // 81920 B
#define NCHUNK (DIM / BK)              // 32

template<bool QKV>
__global__ __launch_bounds__(256, 2) void gemm_f16_kernel(
    const __half* __restrict__ A, const __half* __restrict__ BT,
    void* __restrict__ Cv, int ldc, __half* __restrict__ VT)
{
    extern __shared__ char sm[];
    const uint32_t sbase = smem_u32(sm);
    const int tid = threadIdx.x;
    const int wid = tid >> 5;
    const int lid = tid & 31;
    const int wm  = wid >> 2;
    const int wn  = wid & 3;
    const int g   = lid >> 2;
    const int tg  = lid & 3;
    const int bm = blockIdx.y * BM;
    const int bn = blockIdx.x * BN;

    const int xr16 = lid & 15;
    const uint32_t xh16 = (uint32_t)((lid >> 4) * 16);
    const int bq = lid >> 3, br = lid & 7;
    const uint32_t bRow = (uint32_t)(((bq >> 1) * 8) + br);
    const uint32_t bKh  = (uint32_t)((bq & 1) * 16);

    float acc[4][4][4] = {};

    auto load_chunk = [&](int c, int stg) {
        const __half* Ag = A  + (size_t)bm * DIM + c * BK;
        const __half* Bg = BT + (size_t)bn * DIM + c * BK;
        const uint32_t aB = sbase + (uint32_t)stg * STAGE_BYTES;
        const uint32_t bB = aB + TILE_HALF * 2;
        #pragma unroll
        for (int i = 0; i < 2; i++) {
            int idx = tid + i * 256;
            int r = idx >> 2, s = idx & 3;
            uint32_t off = (uint32_t)(r * 80 + s * 16);
            cp16(aB + off, Ag + (size_t)r * DIM + s * 8);
            cp16(bB + off, Bg + (size_t)r * DIM + s * 8);
        }
    };

    auto compute = [&](int stg) {
        const uint32_t aB = sbase + (uint32_t)stg * STAGE_BYTES;
        const uint32_t bB = aB + TILE_HALF * 2;
        const uint32_t aLane = aB + (uint32_t)(wm * 64 + xr16) * 80 + xh16;
        const uint32_t bLane = bB + (uint32_t)(wn * 32) * 80 + bRow * 80 + bKh;
        #pragma unroll
        for (int kk = 0; kk < 2; kk++) {
            const uint32_t koff = (uint32_t)kk * 32;
            uint32_t af[4][4], bf[4][2];
            #pragma unroll
            for (int fm = 0; fm < 4; fm++)
                ldsm4(af[fm][0], af[fm][1], af[fm][2], af[fm][3],
                      aLane + (uint32_t)(fm * 16) * 80 + koff);
            #pragma unroll
            for (int fnp = 0; fnp < 2; fnp++) {
                uint32_t r0, r1, r2, r3;
                ldsm4(r0, r1, r2, r3, bLane + (uint32_t)(fnp * 16) * 80 + koff);
                bf[2*fnp][0]   = r0; bf[2*fnp][1]   = r1;
                bf[2*fnp+1][0] = r2; bf[2*fnp+1][1] = r3;
            }
            #pragma unroll
            for (int fm = 0; fm < 4; fm++)
                #pragma unroll
                for (int fn = 0; fn < 4; fn++)
                    mma_f16(acc[fm][fn], af[fm][0], af[fm][1], af[fm][2], af[fm][3],
                            bf[fn][0], bf[fn][1]);
        }
    };

    load_chunk(0, 0); CP_COMMIT();
    load_chunk(1, 1); CP_COMMIT();
    load_chunk(2, 2); CP_COMMIT();
    for (int c = 0; c < NCHUNK; c++) {
        // chunk c ready when <= (#groups issued beyond c) outstanding
        if (c <= NCHUNK - 3)      { CP_WAIT2(); }
        else if (c == NCHUNK - 2) { CP_WAIT1(); }
        else                      { CP_WAIT0(); }
        __syncthreads();          // single barrier: stage (c+3)%4 free (read at c-1)
        compute(c & 3);
        if (c + 3 < NCHUNK) { load_chunk(c + 3, (c + 3) & 3); CP_COMMIT(); }
    }

    if (QKV) {
        if (bn >= 2 * DIM) {
            #pragma unroll
            for (int fm = 0; fm < 4; fm++) {
                const int row = bm + wm * 64 + fm * 16 + g;
                const int bb = row >> 11, s = row & (SEQ - 1);
                #pragma unroll
                for (int fn = 0; fn < 4; fn++) {
                    const int colv = (bn - 2 * DIM) + wn * 32 + fn * 8 + tg * 2;
                    const int h = colv >> 6, d = colv & 63;
                    __half* vb = VT + ((size_t)((bb * HEADS + h) * HDIM + d)) * SEQ;
                    vb[s]           = __float2half_rn(acc[fm][fn][0]);
                    vb[SEQ + s]     = __float2half_rn(acc[fm][fn][1]);
                    vb[s + 8]       = __float2half_rn(acc[fm][fn][2]);
                    vb[SEQ + s + 8] = __float2half_rn(acc[fm][fn][3]);
                }
            }
        } else {
            __half* C = (__half*)Cv;
            #pragma unroll
            for (int fm = 0; fm < 4; fm++) {
                const int row = bm + wm * 64 + fm * 16 + g;
                #pragma unroll
                for (int fn = 0; fn < 4; fn++) {
                    const int col = bn + wn * 32 + fn * 8 + tg * 2;
                    *(__half2*)(C + (size_t)row * ldc + col) =
                        __floats2half2_rn(acc[fm][fn][0], acc[fm][fn][1]);
                    *(__half2*)(C + (size_t)(row + 8) * ldc + col) =
                        __floats2half2_rn(acc[fm][fn][2], acc[fm][fn][3]);
                }
            }
        }
        return;
    }

    float* C = (float*)Cv;
    #pragma unroll
    for (int fm = 0; fm < 4; fm++) {
        const int row = bm + wm * 64 + fm * 16 + g;
        #pragma unroll
        for (int fn = 0; fn < 4; fn++) {
            const int col = bn + wn * 32 + fn * 8 + tg * 2;
            *(float2*)(C + (size_t)row * ldc + col) =
                make_float2(acc[fm][fn][0], acc[fm][fn][1]);
            *(float2*)(C + (size_t)(row + 8) * ldc + col) =
                make_float2(acc[fm][fn][2], acc[fm][fn][3]);
        }
    }
}

// ---------------------------------------------------------------------------
// fp16 flash attention, deep-staged + single barrier per KV tile.
// K 3-stage, V 4-stage, P double-buffered, mask 3-stage.
// Iter i: S(i) -> PV(i-1) -> softmax(i) -> prefetch KV(i+2).
// ---------------------------------------------------------------------------
#define AKEYS 64
#define KS_B   0                        // 3 x 9216 = 27648
#define VS_B   27648                    // 4 x 9216 = 36864
#define PS_B   64512                    // 2 x 18432 = 36864 (Q staged in buf 0)
#define MSK_B  101376                   // 3 x 256
#define ATT_SMEM 102144
#define NKT (SEQ / AKEYS)               // 32

__global__ __launch_bounds__(256, 2) void attn_f16_kernel(
    const __half* __restrict__ qk, const __half* __restrict__ vt,
    const int* __restrict__ mask, __half* __restrict__ o)
{
    extern __shared__ char sA[];
    const uint32_t sbase = smem_u32(sA);

    const int b  = blockIdx.z;
    const int h  = blockIdx.y;
    const int qt = blockIdx.x;
    const int tid = threadIdx.x;
    const int w   = tid >> 5;
    const int lid = tid & 31;
    const int g   = lid >> 2;
    const int tg  = lid & 3;
    const int xr16 = lid & 15;
    const uint32_t xh16 = (uint32_t)((lid >> 4) * 16);
    const int bq = lid >> 3, br = lid & 7;
    const uint32_t bRowOff = (uint32_t)(((bq >> 1) * 8) + br) * 144 +
                             (uint32_t)((bq & 1) * 16);

    const int qr0 = w * 16 + g;
    const int qr1 = qr0 + 8;

    // ---- KV tile loader: K+msk stage it%3, V stage it%4, one commit group ----
    auto load_kv = [&](int it) {
        const __half* Kg = qk + ((size_t)(b * SEQ + it * AKEYS)) * QKLD + DIM + h * HDIM;
        const __half* Vg = vt + ((size_t)((b * HEADS + h) * HDIM)) * SEQ + it * AKEYS;
        const uint32_t kB = sbase + KS_B + (uint32_t)(it % 3) * 9216;
        const uint32_t vB = sbase + VS_B + (uint32_t)(it & 3) * 9216;
        #pragma unroll
        for (int i = 0; i < 2; i++) {
            int idx = tid + i * 256;
            int r = idx >> 3, s = idx & 7;
            uint32_t off = (uint32_t)(r * 144 + s * 16);
            cp16(kB + off, Kg + (size_t)r * QKLD + s * 8);
            cp16(vB + off, Vg + (size_t)r * SEQ + s * 8);
        }
        if (tid < 16)
            cp16(sbase + MSK_B + (uint32_t)(it % 3) * 256 + (uint32_t)tid * 16,
                 mask + b * SEQ + it * AKEYS + tid * 4);
    };

    // ---- prologue: Q into P buffer 0; prefetch KV(0), KV(1) ----
    const __half* Qg = qk + ((size_t)(b * SEQ + qt * 128)) * QKLD + h * HDIM;
    #pragma unroll
    for (int i = 0; i < 4; i++) {
        int idx = tid + i * 256;
        int r = idx >> 3, s = idx & 7;
        cp16(sbase + PS_B + (uint32_t)(r * 144 + s * 16), Qg + (size_t)r * QKLD + s * 8);
    }
    CP_COMMIT();
    load_kv(0); CP_COMMIT();
    load_kv(1); CP_COMMIT();
    CP_WAIT2();                 // Q group done
    __syncthreads();

    uint32_t aq[4][4];
    {
        const uint32_t qLane = sbase + PS_B + (uint32_t)(w * 16 + xr16) * 144 + xh16;
        #pragma unroll
        for (int ks = 0; ks < 4; ks++)
            ldsm4(aq[ks][0], aq[ks][1], aq[ks][2], aq[ks][3],
                  qLane + (uint32_t)ks * 32);
    }
    __syncthreads();            // Q frags read; P buffer 0 reusable

    float m0 = -3.0e38f, m1 = -3.0e38f, l0 = 0.0f, l1 = 0.0f;
    float oacc[8][4] = {};

    for (int it = 0; it < NKT; it++) {
        if (it <= NKT - 2) { CP_WAIT1(); } else { CP_WAIT0(); }
        __syncthreads();        // single barrier per tile

        const uint32_t kTile = sbase + KS_B + (uint32_t)(it % 3) * 9216;
        const int* Mi = (const int*)(sA + MSK_B + (it % 3) * 256);

        // ---- S = Q @ K^T (log2 units; Q pre-scaled) ----
        float sacc[8][4] = {};
        #pragma unroll
        for (int ntp = 0; ntp < 4; ntp++) {
            const uint32_t kNtp = kTile + bRowOff + (uint32_t)(ntp * 16) * 144;
            #pragma unroll
            for (int ks = 0; ks < 4; ks++) {
                uint32_t r0, r1, r2, r3;
                ldsm4(r0, r1, r2, r3, kNtp + (uint32_t)ks * 32);
                mma_f16(sacc[2*ntp],   aq[ks][0], aq[ks][1], aq[ks][2], aq[ks][3], r0, r1);
                mma_f16(sacc[2*ntp+1], aq[ks][0], aq[ks][1], aq[ks][2], aq[ks][3], r2, r3);
            }
        }

        // ---- PV(it-1): overlaps softmax below ----
        if (it > 0) {
            const uint32_t vPrev = sbase + VS_B + (uint32_t)((it - 1) & 3) * 9216;
            const uint32_t pPrev = sbase + PS_B + (uint32_t)((it - 1) & 1) * 18432 +
                                   (uint32_t)(w * 16 + xr16) * 144 + xh16;
            #pragma unroll
            for (int kt = 0; kt < 4; kt++) {
                uint32_t a0, a1, a2, a3;
                ldsm4(a0, a1, a2, a3, pPrev + (uint32_t)kt * 32);
                #pragma unroll
                for (int dtp = 0; dtp < 4; dtp++) {
                    uint32_t v0, v1, v2, v3;
                    ldsm4(v0, v1, v2, v3,
                          vPrev + bRowOff + (uint32_t)(dtp * 16) * 144 + (uint32_t)kt * 32);
                    mma_f16(oacc[2*dtp],   a0, a1, a2, a3, v0, v1);
                    mma_f16(oacc[2*dtp+1], a0, a1, a2, a3, v2, v3);
                }
            }
        }

        // ---- softmax(it) ----
        #pragma unroll
        for (int nt = 0; nt < 8; nt++) {
            int c = nt * 8 + 2 * tg;
            if (Mi[c]     == 0) { sacc[nt][0] = -3.0e38f; sacc[nt][2] = -3.0e38f; }
            if (Mi[c + 1] == 0) { sacc[nt][1] = -3.0e38f; sacc[nt][3] = -3.0e38f; }
        }
        float tm0 = -3.0e38f, tm1 = -3.0e38f;
        #pragma unroll
        for (int nt = 0; nt < 8; nt++) {
            tm0 = fmaxf(tm0, fmaxf(sacc[nt][0], sacc[nt][1]));
            tm1 = fmaxf(tm1, fmaxf(sacc[nt][2], sacc[nt][3]));
        }
        tm0 = fmaxf(tm0, __shfl_xor_sync(0xffffffffu, tm0, 1));
        tm0 = fmaxf(tm0, __shfl_xor_sync(0xffffffffu, tm0, 2));
        tm1 = fmaxf(tm1, __shfl_xor_sync(0xffffffffu, tm1, 1));
        tm1 = fmaxf(tm1, __shfl_xor_sync(0xffffffffu, tm1, 2));

        float mn0 = fmaxf(m0, tm0), mn1 = fmaxf(m1, tm1);
        float corr0 = exp2f(m0 - mn0), corr1 = exp2f(m1 - mn1);
        m0 = mn0; m1 = mn1;

        const uint32_t pCur = (uint32_t)(PS_B + (it & 1) * 18432);
        float sum0 = 0.0f, sum1 = 0.0f;
        #pragma unroll
        for (int nt = 0; nt < 8; nt++) {
            float p0 = exp2f(sacc[nt][0] - mn0);
            float p1 = exp2f(sacc[nt][1] - mn0);
            float p2 = exp2f(sacc[nt][2] - mn1);
            float p3 = exp2f(sacc[nt][3] - mn1);
            sum0 += p0 + p1; sum1 += p2 + p3;
            int c = nt * 8 + 2 * tg;
            *(__half2*)(sA + pCur + (qr0 * 144 + c * 2)) = __floats2half2_rn(p0, p1);
            *(__half2*)(sA + pCur + (qr1 * 144 + c * 2)) = __floats2half2_rn(p2, p3);
        }
        sum0 += __shfl_xor_sync(0xffffffffu, sum0, 1);
        sum0 += __shfl_xor_sync(0xffffffffu, sum0, 2);
        sum1 += __shfl_xor_sync(0xffffffffu, sum1, 1);
        sum1 += __shfl_xor_sync(0xffffffffu, sum1, 2);
        l0 = l0 * corr0 + sum0;
        l1 = l1 * corr1 + sum1;

        // ---- rescale oacc (after PV(it-1) accumulated) ----
        #pragma unroll
        for (int dt = 0; dt < 8; dt++) {
            oacc[dt][0] *= corr0; oacc[dt][1] *= corr0;
            oacc[dt][2] *= corr1; oacc[dt][3] *= corr1;
        }

        // ---- prefetch KV(it+2): K stage (it-1)%3, V stage (it-2)%4 — both free
        if (it + 2 < NKT) { load_kv(it + 2); CP_COMMIT(); }
    }

    // ---- final PV(NKT-1) ----
    __syncwarp();
    {
        const uint32_t vPrev = sbase + VS_B + (uint32_t)((NKT - 1) & 3) * 9216;
        const uint32_t pPrev = sbase + PS_B + (uint32_t)((NKT - 1) & 1) * 18432 +
                               (uint32_t)(w * 16 + xr16) * 144 + xh16;
        #pragma unroll
        for (int kt = 0; kt < 4; kt++) {
            uint32_t a0, a1, a2, a3;
            ldsm4(a0, a1, a2, a3, pPrev + (uint32_t)kt * 32);
            #pragma unroll
            for (int dtp = 0; dtp < 4; dtp++) {
                uint32_t v0, v1, v2, v3;
                ldsm4(v0, v1, v2, v3,
                      vPrev + bRowOff + (uint32_t)(dtp * 16) * 144 + (uint32_t)kt * 32);
                mma_f16(oacc[2*dtp],   a0, a1, a2, a3, v0, v1);
                mma_f16(oacc[2*dtp+1], a0, a1, a2, a3, v2, v3);
            }
        }
    }

    // ---- epilogue: normalize, store fp16 ----
    const float inv0 = 1.0f / l0, inv1 = 1.0f / l1;
    __half* Og = o + ((size_t)(b * SEQ + qt * 128)) * DIM + h * HDIM;
    #pragma unroll
    for (int dt = 0; dt < 8; dt++) {
        int c = dt * 8 + 2 * tg;
        *(__half2*)(Og + (size_t)qr0 * DIM + c) =
            __floats2half2_rn(oacc[dt][0] * inv0, oacc[dt][1] * inv0);
        *(__half2*)(Og + (size_t)qr1 * DIM + c) =
            __floats2half2_rn(oacc[dt][2] * inv1, oacc[dt][3] * inv1);
    }
}

// ---------------------------------------------------------------------------
// kernel_launch
// ---------------------------------------------------------------------------
extern "C" void kernel_launch(void* const* d_in, const int* in_sizes, int n_in,
                              void* d_out, int out_size)
{
    const float* H    = (const float*)d_in[0];
    const int*   mask = (const int*)  d_in[1];
    const float* Wq   = (const float*)d_in[2];
    const float* Wk   = (const float*)d_in[3];
    const float* Wv   = (const float*)d_in[4];
    const float* Wo   = (const float*)d_in[5];
    float* out = (float*)d_out;

    __half *h16, *w16, *qkp, *vtp, *aop;
    cudaGetSymbolAddress((void**)&h16, g_h16);
    cudaGetSymbolAddress((void**)&w16, g_w16);
    cudaGetSymbolAddress((void**)&qkp, g_qk);
    cudaGetSymbolAddress((void**)&vtp, g_vt);
    cudaGetSymbolAddress((void**)&aop, g_ao);
    __half* wto = w16 + 3 * DIM * DIM;

    cudaFuncSetAttribute(gemm_f16_kernel<true>,
                         cudaFuncAttributeMaxDynamicSharedMemorySize, GEMM_SMEM);
    cudaFuncSetAttribute(gemm_f16_kernel<false>,
                         cudaFuncAttributeMaxDynamicSharedMemorySize, GEMM_SMEM);
    cudaFuncSetAttribute(attn_f16_kernel,
                         cudaFuncAttributeMaxDynamicSharedMemorySize, ATT_SMEM);

    dim3 tb(32, 8), tg(DIM / 32, DIM / 32, 8);
    prep_kernel<<<tg, tb>>>(H, Wq, Wk, Wv, Wo, w16, h16);

    dim3 gqkv(3 * DIM / BN, MROWS / BM);   // (24, 32)
    gemm_f16_kernel<true><<<gqkv, 256, GEMM_SMEM>>>(h16, w16, qkp, QKLD, vtp);

    dim3 ga(SEQ / 128, HEADS, BATCH);      // (16, 16, 2)
    attn_f16_kernel<<<ga, 256, ATT_SMEM>>>(qkp, vtp, mask, aop);

    dim3 go(DIM / BN, MROWS / BM);         // (8, 32)
    gemm_f16_kernel<false><<<go, 256, GEMM_SMEM>>>(aop, wto, out, DIM, nullptr);
}